// round 11
// baseline (speedup 1.0000x reference)
#include <cuda_runtime.h>
#include <cuda_bf16.h>
#include <cstddef>
#include <cstdint>

// Problem constants
#define NB    2
#define SLEN  2048
#define EMB   1024            // H=16, D=64
#define NBLK  128             // persistent grid: 1 block/SM, uniform placement
#define THR   1024
#define CPN   64              // partial chunks per batch (32 rows each)
#define SLAB_BYTES  131072    // 32 rows x 4 KB
#define WO_BYTES    32768     // 8 Wo rows
#define SMEM_BYTES  (SLAB_BYTES + WO_BYTES)

// Scratch (__device__ globals; no allocation). Zero-init counters/flags;
// the last exiting block resets them -> graph-replay safe.
__device__ float g_part[NB][CPN][EMB];  // per-chunk column-sum partials (512 KB)
__device__ float g_t[NB][EMB];          // t = blockdiag(Wv) @ sv
__device__ int   g_c1, g_c2, g_ce;
__device__ volatile int g_f1, g_f2;

// ---- PTX helpers: mbarrier + cp.async.bulk --------------------------------
__device__ __forceinline__ void mbar_init(uint32_t mb, uint32_t cnt) {
    asm volatile("mbarrier.init.shared.b64 [%0], %1;" :: "r"(mb), "r"(cnt) : "memory");
}
__device__ __forceinline__ void mbar_expect_tx(uint32_t mb, uint32_t bytes) {
    asm volatile("mbarrier.arrive.expect_tx.shared.b64 _, [%0], %1;"
                 :: "r"(mb), "r"(bytes) : "memory");
}
__device__ __forceinline__ void bulk_ld(uint32_t sdst, const void* gsrc,
                                        uint32_t bytes, uint32_t mb) {
    asm volatile(
        "cp.async.bulk.shared::cta.global.mbarrier::complete_tx::bytes [%0], [%1], %2, [%3];"
        :: "r"(sdst), "l"(gsrc), "r"(bytes), "r"(mb) : "memory");
}
__device__ __forceinline__ void mbar_wait(uint32_t mb, uint32_t parity) {
    uint32_t done;
    asm volatile(
        "{\n .reg .pred p;\n"
        " mbarrier.try_wait.parity.acquire.cta.shared::cta.b64 p, [%1], %2;\n"
        " selp.b32 %0, 1, 0, p;\n}"
        : "=r"(done) : "r"(mb), "r"(parity) : "memory");
    while (!done) {
        asm volatile(
            "{\n .reg .pred p;\n"
            " mbarrier.try_wait.parity.acquire.cta.shared::cta.b64 p, [%1], %2, 0x989680;\n"
            " selp.b32 %0, 1, 0, p;\n}"
            : "=r"(done) : "r"(mb), "r"(parity) : "memory");
    }
}

__global__ void __launch_bounds__(THR, 1)
k_fused(const float* __restrict__ vals,
        const float* __restrict__ Wv,
        const float* __restrict__ Wo,
        const float* __restrict__ bo,
        float*       __restrict__ out)
{
    extern __shared__ __align__(128) float4 s_dyn[];   // [0,8192): slab
                                                       // [8192,10240): Wo rows
    __shared__ uint64_t s_mbar;
    __shared__ float  s_part3[NB][8][4];
    __shared__ float4 s_y4[NB][2];                     // y chunk (8 floats/batch)

    const int b   = blockIdx.x;
    const int tid = threadIdx.x;
    const uint32_t sbuf = (uint32_t)__cvta_generic_to_shared(s_dyn);
    const uint32_t mb0  = (uint32_t)__cvta_generic_to_shared(&s_mbar);

    // ======================= P1: column-sum partials =======================
    // Block b: batch n = b>>6, 32-row slab c = b&63 (128 KB). Issue all 4
    // 32 KB bulk loads at once (parity 0), wait once, accumulate from SMEM.
    {
        const int n = b >> 6;
        const int c = b & 63;
        const float* __restrict__ slab = vals + (size_t)(n * SLEN + c * 32) * EMB;

        if (tid == 0) {
            mbar_init(mb0, 1);
            asm volatile("fence.proxy.async.shared::cta;" ::: "memory");
            mbar_expect_tx(mb0, SLAB_BYTES);
            #pragma unroll
            for (int r = 0; r < 4; ++r)
                bulk_ld(sbuf + r * 32768, slab + r * 8192, 32768, mb0);
        }
        __syncthreads();
        mbar_wait(mb0, 0);

        const int rg  = tid >> 8;      // rowgroup 0..3 (8 rows each)
        const int col = tid & 255;
        float4 acc = make_float4(0.f, 0.f, 0.f, 0.f);
        #pragma unroll
        for (int s = 0; s < 8; ++s) {
            const float4 v = s_dyn[(rg * 8 + s) * 256 + col];
            acc.x += v.x; acc.y += v.y; acc.z += v.z; acc.w += v.w;
        }
        __syncthreads();
        s_dyn[tid] = acc;
        __syncthreads();
        if (tid < 256) {
            float4 a0 = s_dyn[tid];
            const float4 a1 = s_dyn[256 + tid];
            const float4 a2 = s_dyn[512 + tid];
            const float4 a3 = s_dyn[768 + tid];
            a0.x = (a0.x + a1.x) + (a2.x + a3.x);
            a0.y = (a0.y + a1.y) + (a2.y + a3.y);
            a0.z = (a0.z + a1.z) + (a2.z + a3.z);
            a0.w = (a0.w + a1.w) + (a2.w + a3.w);
            ((float4*)g_part[n][c])[tid] = a0;
        }
    }

    // ---- bar1 arrive (non-blocking for all; only P2 blocks will wait) ----
    __syncthreads();
    if (tid == 0) {
        __threadfence();
        if (atomicAdd(&g_c1, 1) == NBLK - 1) g_f1 = 1;
        // overlap: prefetch this block's 8 Wo rows (parity 1) during waits
        mbar_expect_tx(mb0, WO_BYTES);
        bulk_ld(sbuf + SLAB_BYTES, Wo + (size_t)b * 8 * EMB, WO_BYTES, mb0);
    }

    // ================= P2 (32 blocks): partials -> sv -> t =================
    if (b < 32) {
        if (tid == 0) {
            while (g_f1 == 0) { __nanosleep(32); }
            __threadfence();
        }
        __syncthreads();

        const int n = b >> 4;
        const int h = b & 15;
        const int c = tid >> 4;        // chunk 0..63
        const int L = tid & 15;        // float4 col within the head

        s_dyn[c * 16 + L] = __ldcg(&((const float4*)g_part[n][c])[h * 16 + L]);
        __syncthreads();
        #pragma unroll
        for (int st = 32; st >= 1; st >>= 1) {
            if (c < st) {
                float4 a = s_dyn[c * 16 + L], d2 = s_dyn[(c + st) * 16 + L];
                a.x += d2.x; a.y += d2.y; a.z += d2.z; a.w += d2.w;
                s_dyn[c * 16 + L] = a;
            }
            __syncthreads();
        }
        if (tid < 64) {
            const float* __restrict__ svh  = (const float*)s_dyn;  // 64 floats
            const float* __restrict__ wrow = Wv + tid * 64;
            float acc = 0.f;
            #pragma unroll 16
            for (int dp = 0; dp < 64; ++dp) acc += __ldg(&wrow[dp]) * svh[dp];
            g_t[n][h * 64 + tid] = acc;
        }
        __syncthreads();
        if (tid == 0) {
            __threadfence();
            if (atomicAdd(&g_c2, 1) == 31) g_f2 = 1;
        }
    }

    // ---------------- wait for t (flag 2) + Wo prefetch ----------------
    if (tid == 0) {
        while (g_f2 == 0) { __nanosleep(32); }
        __threadfence();
    }
    __syncthreads();
    mbar_wait(mb0, 1);                  // Wo rows resident in SMEM

    // ====== P3: y[8b..8b+8) = Wo_rows @ t + bo (both batches), in-block =====
    {
        const int e0   = b * 8;
        const int w    = tid >> 5;       // warp 0..31
        const int lane = tid & 31;
        const int el   = w >> 2;         // e-local 0..7
        const int q    = w & 3;          // quarter (64 float4 each)

        const float4* __restrict__ worow = s_dyn + 8192 + el * 256 + q * 64;
        const float4* __restrict__ t0 = (const float4*)g_t[0] + q * 64;
        const float4* __restrict__ t1 = (const float4*)g_t[1] + q * 64;

        float a0 = 0.f, a1 = 0.f;
        #pragma unroll
        for (int i = lane; i < 64; i += 32) {
            float4 wv = worow[i];
            float4 x  = __ldcg(&t0[i]);
            float4 z  = __ldcg(&t1[i]);
            a0 += wv.x * x.x + wv.y * x.y + wv.z * x.z + wv.w * x.w;
            a1 += wv.x * z.x + wv.y * z.y + wv.z * z.z + wv.w * z.w;
        }
        #pragma unroll
        for (int o = 16; o; o >>= 1) {
            a0 += __shfl_xor_sync(0xFFFFFFFFu, a0, o);
            a1 += __shfl_xor_sync(0xFFFFFFFFu, a1, o);
        }
        if (lane == 0) {
            s_part3[0][el][q] = a0;
            s_part3[1][el][q] = a1;
        }
        __syncthreads();
        if (tid < 16) {                   // n = tid>>3, e-local = tid&7
            const int nn = tid >> 3;
            const int ee = tid & 7;
            ((float*)s_y4[nn])[ee] = ((s_part3[nn][ee][0] + s_part3[nn][ee][1])
                                    + (s_part3[nn][ee][2] + s_part3[nn][ee][3]))
                                   + __ldg(&bo[e0 + ee]);
        }
        __syncthreads();
    }

    // ====== P4 (fused): scatter this block's 32B y-chunk to all rows ======
    {
        const float4 y0lo = s_y4[0][0], y0hi = s_y4[0][1];
        const float4 y1lo = s_y4[1][0], y1hi = s_y4[1][1];

        float4* __restrict__ o4 = (float4*)out;
        const size_t cb = (size_t)b * 2;            // float4 column offset

        #pragma unroll
        for (int k = 0; k < 2; ++k) {
            const size_t r  = (size_t)tid + (size_t)k * 1024;
            const size_t i0 = (r << 8) + cb;                 // batch 0
            const size_t i1 = i0 + ((size_t)SLEN << 8);      // batch 1
            o4[i0]     = y0lo;
            o4[i0 + 1] = y0hi;
            o4[i1]     = y1lo;
            o4[i1 + 1] = y1hi;
        }
    }

    // ======================= exit: reset for replay ========================
    __threadfence();
    __syncthreads();
    if (tid == 0) {
        if (atomicAdd(&g_ce, 1) == NBLK - 1) {
            g_c1 = 0; g_c2 = 0; g_ce = 0;
            g_f1 = 0; g_f2 = 0;
        }
    }
}

// ---------------------------------------------------------------------------
// Inputs (metadata order): 0=values 1=keys 2=queries 3=mask 4=Wv 5=Wk 6=Wq
//                          7=Wo 8=bo.   Output: float32 [2, 2048, 1024].
// ---------------------------------------------------------------------------
extern "C" void kernel_launch(void* const* d_in, const int* in_sizes, int n_in,
                              void* d_out, int out_size)
{
    const float* values = (const float*)d_in[0];
    const float* Wv     = (const float*)d_in[4];
    const float* Wo     = (const float*)d_in[7];
    const float* bo     = (const float*)d_in[8];
    float*       out    = (float*)d_out;

    cudaFuncSetAttribute(k_fused, cudaFuncAttributeMaxDynamicSharedMemorySize,
                         SMEM_BYTES);
    k_fused<<<NBLK, THR, SMEM_BYTES>>>(values, Wv, Wo, bo, out);
}

// round 12
// speedup vs baseline: 1.0977x; 1.0977x over previous
#include <cuda_runtime.h>
#include <cuda_bf16.h>
#include <cstddef>
#include <cstdint>

// Problem constants
#define NB    2
#define SLEN  2048
#define EMB   1024            // H=16, D=64
#define NBLK  256             // persistent grid (co-resident: 148 SMs x 2)
#define THR   512
#define CPN   256             // partial chunks per batch (8 rows each)
#define RPB   8               // rows per partial chunk

// Scratch (__device__ globals; no allocation). Zero-init counters/flags;
// the last exiting block resets them -> graph-replay safe.
__device__ float g_part[NB][CPN][EMB];  // per-chunk column-sum partials (2 MB)
__device__ float g_t[NB][EMB];          // t = blockdiag(Wv) @ sv
__device__ float g_y[NB][EMB];          // y = Wo @ t + bo
__device__ int   g_c1, g_c2, g_c3, g_ce;
__device__ volatile int g_f1, g_f2, g_f3;

// ---- cp.async helpers ------------------------------------------------------
__device__ __forceinline__ void cp_async16(uint32_t saddr, const void* gaddr) {
    asm volatile("cp.async.cg.shared.global [%0], [%1], 16;"
                 :: "r"(saddr), "l"(gaddr) : "memory");
}
__device__ __forceinline__ void cp_async_commit() {
    asm volatile("cp.async.commit_group;" ::: "memory");
}
__device__ __forceinline__ void cp_async_wait0() {
    asm volatile("cp.async.wait_group 0;" ::: "memory");
}

__global__ void __launch_bounds__(THR, 2)
k_fused(const float* __restrict__ vals,
        const float* __restrict__ Wv,
        const float* __restrict__ Wo,
        const float* __restrict__ bo,
        float*       __restrict__ out)
{
    const int b   = blockIdx.x;
    const int tid = threadIdx.x;

    __shared__ __align__(16) float4 s_wo[1024];   // 16 KB: 4 Wo rows
    __shared__ __align__(16) float4 s_p2[512];    // 8 KB: P2 tree
    __shared__ float s_part3[NB][4][4];

    const uint32_t swo = (uint32_t)__cvta_generic_to_shared(s_wo);

    // ======================= P1: column-sum partials =======================
    // Block b: batch n = b>>7, chunks 2*(b&127)+{0,1}; halves of the block
    // each sum one 8-row chunk (MLP=8).
    {
        const int n   = b >> 7;
        const int c   = ((b & 127) << 1) + (tid >> 8);  // chunk 0..255
        const int col = tid & 255;                      // float4 lane
        const float4* __restrict__ base =
            (const float4*)(vals + (size_t)n * SLEN * EMB + (size_t)c * RPB * EMB);

        float4 acc = make_float4(0.f, 0.f, 0.f, 0.f);
        #pragma unroll
        for (int s = 0; s < RPB; ++s) {
            float4 v = __ldg(&base[s * (EMB / 4) + col]);
            acc.x += v.x; acc.y += v.y; acc.z += v.z; acc.w += v.w;
        }
        ((float4*)g_part[n][c])[col] = acc;
    }

    // ---- bar1 arrive (non-blocking) + Wo prefetch overlapped with waits ----
    __syncthreads();
    // prefetch this block's 4 Wo rows (16 KB) into smem: 2 x 16B per thread
    {
        const float4* __restrict__ wsrc = (const float4*)(Wo + (size_t)b * 4 * EMB);
        cp_async16(swo + (uint32_t)tid * 16,         wsrc + tid);
        cp_async16(swo + (uint32_t)(tid + 512) * 16, wsrc + tid + 512);
        cp_async_commit();
    }
    if (tid == 0) {
        __threadfence();
        if (atomicAdd(&g_c1, 1) == NBLK - 1) g_f1 = 1;
    }

    // ================= P2 (32 blocks): partials -> sv -> t =================
    // Block (n = b>>4, head h = b&15). 512 threads = 32 c-splits x 16 cols.
    if (b < 32) {
        if (tid == 0) {
            while (g_f1 == 0) {}
            __threadfence();
        }
        __syncthreads();

        const int n  = b >> 4;
        const int h  = b & 15;
        const int L  = tid & 15;       // float4 col within the head
        const int cs = tid >> 4;       // 0..31 c-split (8 chunks each)

        float4 p = make_float4(0.f, 0.f, 0.f, 0.f);
        #pragma unroll
        for (int k = 0; k < 8; ++k) {
            const int c = cs * 8 + k;
            float4 v = __ldcg(&((const float4*)g_part[n][c])[h * 16 + L]);
            p.x += v.x; p.y += v.y; p.z += v.z; p.w += v.w;
        }
        s_p2[cs * 16 + L] = p;
        __syncthreads();
        #pragma unroll
        for (int st = 16; st >= 1; st >>= 1) {
            if (cs < st) {
                float4 a = s_p2[cs * 16 + L], d2 = s_p2[(cs + st) * 16 + L];
                a.x += d2.x; a.y += d2.y; a.z += d2.z; a.w += d2.w;
                s_p2[cs * 16 + L] = a;
            }
            __syncthreads();
        }
        if (tid < 64) {
            const float* __restrict__ svh  = (const float*)s_p2;   // 64 floats
            const float* __restrict__ wrow = Wv + tid * 64;
            float acc = 0.f;
            #pragma unroll 16
            for (int dp = 0; dp < 64; ++dp) acc += __ldg(&wrow[dp]) * svh[dp];
            g_t[n][h * 64 + tid] = acc;
        }
        __syncthreads();
        if (tid == 0) {
            __threadfence();
            if (atomicAdd(&g_c2, 1) == 31) g_f2 = 1;
        }
    }

    // ---------------- all blocks: wait for t, Wo now in smem ----------------
    if (tid == 0) {
        while (g_f2 == 0) {}
        __threadfence();
    }
    __syncthreads();
    cp_async_wait0();
    __syncthreads();

    // ===== P3: y[4b..4b+4) = s_wo @ t + bo (both batches), Wo from SMEM =====
    {
        const int e0   = b * 4;
        const int w    = tid >> 5;       // warp 0..15
        const int lane = tid & 31;
        const int el   = w >> 2;         // e-local 0..3
        const int q    = w & 3;          // quarter (64 float4 each)

        const float4* __restrict__ worow = s_wo + el * 256 + q * 64;
        const float4* __restrict__ t0 = (const float4*)g_t[0] + q * 64;
        const float4* __restrict__ t1 = (const float4*)g_t[1] + q * 64;

        float a0 = 0.f, a1 = 0.f;
        #pragma unroll
        for (int i = lane; i < 64; i += 32) {
            float4 wv = worow[i];
            float4 x  = __ldcg(&t0[i]);
            float4 z  = __ldcg(&t1[i]);
            a0 += wv.x * x.x + wv.y * x.y + wv.z * x.z + wv.w * x.w;
            a1 += wv.x * z.x + wv.y * z.y + wv.z * z.z + wv.w * z.w;
        }
        #pragma unroll
        for (int o = 16; o; o >>= 1) {
            a0 += __shfl_xor_sync(0xFFFFFFFFu, a0, o);
            a1 += __shfl_xor_sync(0xFFFFFFFFu, a1, o);
        }
        if (lane == 0) {
            s_part3[0][el][q] = a0;
            s_part3[1][el][q] = a1;
        }
        __syncthreads();
        if (tid < 8) {                    // n = tid>>2, e-local = tid&3
            const int nn = tid >> 2;
            const int ee = tid & 3;
            g_y[nn][e0 + ee] = ((s_part3[nn][ee][0] + s_part3[nn][ee][1])
                              + (s_part3[nn][ee][2] + s_part3[nn][ee][3]))
                             + __ldg(&bo[e0 + ee]);
        }
    }

    // ------------------------------ bar3 -----------------------------------
    __syncthreads();
    if (tid == 0) {
        __threadfence();
        if (atomicAdd(&g_c3, 1) == NBLK - 1) {
            g_f3 = 1;
        } else {
            while (g_f3 == 0) {}
        }
        __threadfence();
    }
    __syncthreads();

    // ===================== P4: broadcast y to all rows =====================
    // Block b: batch n = b>>7, 16-row slab; halves write 8 rows each.
    // Streaming stores (evict-first): output is never re-read.
    {
        const int n    = b >> 7;
        const int c    = b & 127;
        const int half = tid >> 8;
        const int col  = tid & 255;
        const float4 v = __ldcg(&((const float4*)g_y[n])[col]);

        float4* __restrict__ dst =
            (float4*)(out + (size_t)n * SLEN * EMB
                          + ((size_t)c * 16 + half * 8) * EMB);
        #pragma unroll
        for (int s = 0; s < 8; ++s)
            __stcs(&dst[s * (EMB / 4) + col], v);
    }

    // ======================= exit: reset for replay ========================
    __threadfence();
    __syncthreads();
    if (tid == 0) {
        if (atomicAdd(&g_ce, 1) == NBLK - 1) {
            g_c1 = 0; g_c2 = 0; g_c3 = 0; g_ce = 0;
            g_f1 = 0; g_f2 = 0; g_f3 = 0;
        }
    }
}

// ---------------------------------------------------------------------------
// Inputs (metadata order): 0=values 1=keys 2=queries 3=mask 4=Wv 5=Wk 6=Wq
//                          7=Wo 8=bo.   Output: float32 [2, 2048, 1024].
// ---------------------------------------------------------------------------
extern "C" void kernel_launch(void* const* d_in, const int* in_sizes, int n_in,
                              void* d_out, int out_size)
{
    const float* values = (const float*)d_in[0];
    const float* Wv     = (const float*)d_in[4];
    const float* Wo     = (const float*)d_in[7];
    const float* bo     = (const float*)d_in[8];
    float*       out    = (float*)d_out;

    k_fused<<<NBLK, THR>>>(values, Wv, Wo, bo, out);
}